// round 17
// baseline (speedup 1.0000x reference)
#include <cuda_runtime.h>
#include <cuda_bf16.h>
#include <mma.h>
#include <math.h>
#include <stdint.h>

using namespace nvcuda;

#define N_NODES 50000
#define N_PAD 50048                   // multiple of 64 for direct wmma stores
#define N_EDGES 600000
#define N_GRAPHS 500
#define HID 128
#define N_LAYERS 3
#define N_CLASSES 10

#define SCAN_B 512
#define SCAN_NB ((N_NODES + SCAN_B - 1) / SCAN_B)   // 98

#define LDAF 132                      // fp32 smem stride (pad 4 floats = 16B)
#define A_ELEMS (64 * LDAF)           // A tile: 64 rows
#define B_ELEMS (128 * LDAF)          // B side-plane: 128 rows
#define SM_A 0
#define SM_B A_ELEMS
#define GEMM_SMEM ((A_ELEMS + B_ELEMS) * 4)   // 101376 B -> 2 CTAs/SM

// ---------------- scratch (device globals; no allocs allowed) ----------------
__device__ int   g_cnt[N_NODES];
__device__ int   g_row[N_NODES + 1];
__device__ int   g_loc[N_EDGES];
__device__ int   g_csr[N_EDGES];
__device__ int   g_bsum[SCAN_NB];
__device__ float g_mean[(size_t)N_PAD * HID];
__device__ float g_h0[(size_t)N_PAD * HID];
__device__ float g_h1[(size_t)N_PAD * HID];
// W tf32-rounded fp32 blobs, padded-LDAF layout: [layer][side][128 x LDAF]
__device__ __align__(16) float g_Wblob[(size_t)N_LAYERS * 2 * B_ELEMS];
// bias tiles: [layer][16 rows][128 cols], rows replicated
__device__ __align__(16) float g_btile[N_LAYERS * 16 * HID];

// ---------------- CSR build: ONE atomic pass + atomic-free scatter -----------
__global__ void count_loc_kernel(const int* __restrict__ dst, int* __restrict__ cnt,
                                 int* __restrict__ loc) {
    int i = (blockIdx.x * blockDim.x + threadIdx.x) * 4;
    if (i + 3 < N_EDGES) {
        int4 d = *(const int4*)(dst + i);
        int4 p;
        p.x = atomicAdd(&cnt[d.x], 1);
        p.y = atomicAdd(&cnt[d.y], 1);
        p.z = atomicAdd(&cnt[d.z], 1);
        p.w = atomicAdd(&cnt[d.w], 1);
        *(int4*)(loc + i) = p;
    } else {
        for (int e = i; e < N_EDGES; e++) loc[e] = atomicAdd(&cnt[dst[e]], 1);
    }
}

__global__ void scan_partial_kernel(const int* __restrict__ cnt, int* __restrict__ bsum) {
    __shared__ int sh[SCAN_B];
    int t = threadIdx.x;
    int i = blockIdx.x * SCAN_B + t;
    sh[t] = (i < N_NODES) ? cnt[i] : 0;
    __syncthreads();
#pragma unroll
    for (int off = SCAN_B / 2; off > 0; off >>= 1) {
        if (t < off) sh[t] += sh[t + off];
        __syncthreads();
    }
    if (t == 0) bsum[blockIdx.x] = sh[0];
}

// fused: per-block offset from bsum + local scan + row write
__global__ void scan_apply_kernel(const int* __restrict__ cnt, const int* __restrict__ bsum,
                                  int* __restrict__ row) {
    __shared__ int sh[SCAN_B];
    __shared__ int sb[128];
    __shared__ int s_boff;
    int t = threadIdx.x;
    int i = blockIdx.x * SCAN_B + t;

    if (t < 128) sb[t] = (t < blockIdx.x && t < SCAN_NB) ? bsum[t] : 0;
    __syncthreads();
    if (t < 64) sb[t] += sb[t + 64];
    __syncthreads();
    if (t < 32) {
        int v = sb[t] + sb[t + 32];
#pragma unroll
        for (int off = 16; off > 0; off >>= 1)
            v += __shfl_down_sync(0xFFFFFFFF, v, off);
        if (t == 0) s_boff = v;
    }

    int v = (i < N_NODES) ? cnt[i] : 0;
    sh[t] = v;
    __syncthreads();
#pragma unroll
    for (int off = 1; off < SCAN_B; off <<= 1) {
        int add = (t >= off) ? sh[t - off] : 0;
        __syncthreads();
        sh[t] += add;
        __syncthreads();
    }
    int excl = s_boff + sh[t] - v;
    if (i < N_NODES) row[i] = excl;
    if (i == N_NODES - 1) row[N_NODES] = excl + v;
}

__global__ void fill_csr_kernel(const int* __restrict__ src, const int* __restrict__ dst,
                                const int* __restrict__ loc, const int* __restrict__ row,
                                int* __restrict__ csr) {
    int i = (blockIdx.x * blockDim.x + threadIdx.x) * 4;
    if (i + 3 < N_EDGES) {
        int4 d = *(const int4*)(dst + i);
        int4 s = *(const int4*)(src + i);
        int4 p = *(const int4*)(loc + i);
        csr[row[d.x] + p.x] = s.x;
        csr[row[d.y] + p.y] = s.y;
        csr[row[d.z] + p.z] = s.z;
        csr[row[d.w] + p.w] = s.w;
    } else {
        for (int e = i; e < N_EDGES; e++) csr[row[dst[e]] + loc[e]] = src[e];
    }
}

// ---------------- W prep: fp32 [j][k] -> tf32-rounded fp32 in padded layout --
__global__ void prep_w_kernel(const float* __restrict__ Wl, const float* __restrict__ Wr,
                              float* __restrict__ blob) {
    int i = blockIdx.x * blockDim.x + threadIdx.x;   // one float4 per thread
    if (i >= N_LAYERS * 2 * 128 * 32) return;
    int kq   = i & 31;           // k/4
    int j    = (i >> 5) & 127;
    int side = (i >> 12) & 1;
    int l    = i >> 13;
    int k = kq << 2;
    const float* W = side ? Wr : Wl;
    float4 v = *(const float4*)(W + (size_t)l * 16384 + j * HID + k);
    v.x = wmma::__float_to_tf32(v.x);
    v.y = wmma::__float_to_tf32(v.y);
    v.z = wmma::__float_to_tf32(v.z);
    v.w = wmma::__float_to_tf32(v.w);
    *(float4*)&blob[(size_t)(l * 2 + side) * B_ELEMS + j * LDAF + k] = v;
}

// bias tiles: replicate bias row 16x per layer
__global__ void prep_bias_kernel(const float* __restrict__ bl, float* __restrict__ btile) {
    int i = blockIdx.x * blockDim.x + threadIdx.x;
    if (i >= N_LAYERS * 16 * HID) return;
    int c = i & 127;
    int l = i >> 11;
    btile[i] = bl[l * HID + c];
}

// ---------------- mean aggregation: warp per node, CSR gather ----------------
__global__ void aggregate_kernel(const float* __restrict__ x, float* __restrict__ mean) {
    int w = (blockIdx.x * blockDim.x + threadIdx.x) >> 5;
    int lane = threadIdx.x & 31;
    if (w >= N_NODES) return;
    int beg = g_row[w];
    int end = g_row[w + 1];
    float4 s = make_float4(0.f, 0.f, 0.f, 0.f);
    for (int i = beg; i < end; i++) {
        int sn = g_csr[i];
        float4 v = *(const float4*)(x + (size_t)sn * HID + lane * 4);
        s.x += v.x; s.y += v.y; s.z += v.z; s.w += v.w;
    }
    float ic = 1.0f / fmaxf((float)(end - beg), 1.0f);
    s.x *= ic; s.y *= ic; s.z *= ic; s.w *= ic;
    *(float4*)(mean + (size_t)w * HID + lane * 4) = s;
}

// ---------------- wmma TF32 fused dual GEMM ----------------------------------
// out = relu(mean @ Wl^T + x @ Wr^T + b), fp32 accumulators, single tf32 pass.
// Tile: 64 rows x 128 cols; 8 warps = 2 row groups x 4 col groups (32x32 each).
// A and the active B side-plane both in smem.
__global__ __launch_bounds__(256, 2) void gemm_wmma_kernel(
    const float* __restrict__ xin, const float* __restrict__ mean,
    const float* __restrict__ Wblob,    // layer base: [side][128 x LDAF]
    const float* __restrict__ btile,    // [16][128] replicated bias
    float* __restrict__ xout)           // padded to N_PAD rows
{
    extern __shared__ float smf[];
    const int tid = threadIdx.x;
    const int wid = tid >> 5;
    const int wr = wid >> 2;            // warp row group (0..1): rows wr*32
    const int wc = wid & 3;             // warp col group (0..3): cols wc*32
    const int row0 = blockIdx.x * 64;

    // init accumulators with bias (rows of btile are identical)
    wmma::fragment<wmma::accumulator, 16, 16, 8, float> acc[2][2];
#pragma unroll
    for (int i = 0; i < 2; i++)
#pragma unroll
        for (int j = 0; j < 2; j++)
            wmma::load_matrix_sync(acc[i][j], btile + wc * 32 + j * 16, HID,
                                   wmma::mem_row_major);

    for (int side = 0; side < 2; side++) {
        const float* A = side ? xin : mean;
        const float* B = Wblob + (size_t)side * B_ELEMS;
        __syncthreads();   // previous side's smem fully consumed

        // stage B side-plane: straight uint4 copy (67584 B, already tf32-rounded)
        {
            const uint4* wsrc = (const uint4*)B;
            uint4* wdst = (uint4*)(smf + SM_B);
            for (int i = tid; i < B_ELEMS / 4; i += 256) wdst[i] = wsrc[i];
        }
        // stage A: 64 rows x 128 cols fp32, tf32-rounded
        for (int i = tid; i < 64 * 32; i += 256) {
            int r = i >> 5;
            int c = (i & 31) << 2;
            int gr = row0 + r;
            float4 v = make_float4(0.f, 0.f, 0.f, 0.f);
            if (gr < N_NODES) v = *(const float4*)(A + (size_t)gr * HID + c);
            v.x = wmma::__float_to_tf32(v.x);
            v.y = wmma::__float_to_tf32(v.y);
            v.z = wmma::__float_to_tf32(v.z);
            v.w = wmma::__float_to_tf32(v.w);
            *(float4*)&smf[SM_A + r * LDAF + c] = v;
        }
        __syncthreads();

#pragma unroll
        for (int k = 0; k < HID; k += 8) {
            wmma::fragment<wmma::matrix_a, 16, 16, 8, wmma::precision::tf32,
                           wmma::row_major> a[2];
            wmma::fragment<wmma::matrix_b, 16, 16, 8, wmma::precision::tf32,
                           wmma::col_major> b[2];
#pragma unroll
            for (int i = 0; i < 2; i++) {
                int r = wr * 32 + i * 16;
                wmma::load_matrix_sync(a[i], &smf[SM_A + r * LDAF + k], LDAF);
            }
#pragma unroll
            for (int j = 0; j < 2; j++) {
                int cj = wc * 32 + j * 16;
                wmma::load_matrix_sync(b[j], &smf[SM_B + cj * LDAF + k], LDAF);
            }
#pragma unroll
            for (int i = 0; i < 2; i++)
#pragma unroll
                for (int j = 0; j < 2; j++)
                    wmma::mma_sync(acc[i][j], a[i], b[j], acc[i][j]);
        }
    }

    // epilogue: relu on fragments, direct global store (padded buffer)
#pragma unroll
    for (int i = 0; i < 2; i++)
#pragma unroll
        for (int j = 0; j < 2; j++) {
#pragma unroll
            for (int e = 0; e < acc[i][j].num_elements; e++)
                acc[i][j].x[e] = fmaxf(acc[i][j].x[e], 0.0f);
            int r = row0 + wr * 32 + i * 16;
            int c = wc * 32 + j * 16;
            wmma::store_matrix_sync(&xout[(size_t)r * HID + c], acc[i][j], HID,
                                    wmma::mem_row_major);
        }
}

// ---------------- fused pool + MLP + log_softmax: block per graph -----------
__global__ void pool_mlp_kernel(const float* __restrict__ x, const int* __restrict__ batch,
                                const float* __restrict__ W1, const float* __restrict__ b1,
                                const float* __restrict__ W2, const float* __restrict__ b2,
                                float* __restrict__ out) {
    __shared__ int s_beg, s_end;
    __shared__ float sg[HID];
    __shared__ float sh[HID];
    __shared__ float sl[N_CLASSES];
    int g = blockIdx.x;
    int t = threadIdx.x;
    if (t == 0) {
        int lo = 0, hi = N_NODES;
        while (lo < hi) { int m = (lo + hi) >> 1; if (batch[m] < g) lo = m + 1; else hi = m; }
        s_beg = lo;
    }
    if (t == 1) {
        int lo = 0, hi = N_NODES;
        while (lo < hi) { int m = (lo + hi) >> 1; if (batch[m] < g + 1) lo = m + 1; else hi = m; }
        s_end = lo;
    }
    __syncthreads();
    int beg = s_beg, end = s_end;
    float s = 0.0f;
    for (int n = beg; n < end; n++) s += x[(size_t)n * HID + t];
    sg[t] = fmaxf(s, 0.0f);   // relu(global_add_pool)
    __syncthreads();

    float acc = b1[t];
    const float* w1r = W1 + (size_t)t * HID;
#pragma unroll 8
    for (int k = 0; k < HID; k++) acc += sg[k] * w1r[k];
    sh[t] = fmaxf(acc, 0.0f);
    __syncthreads();

    if (t < N_CLASSES) {
        float a = b2[t];
        const float* w2r = W2 + (size_t)t * HID;
#pragma unroll 8
        for (int k = 0; k < HID; k++) a += sh[k] * w2r[k];
        sl[t] = a;
    }
    __syncthreads();

    if (t == 0) {
        float m = -1e30f;
        for (int c = 0; c < N_CLASSES; c++) m = fmaxf(m, sl[c]);
        float su = 0.0f;
        for (int c = 0; c < N_CLASSES; c++) su += expf(sl[c] - m);
        float lse = m + logf(su);
        for (int c = 0; c < N_CLASSES; c++) out[(size_t)g * N_CLASSES + c] = sl[c] - lse;
    }
}

// ---------------- launch ----------------
extern "C" void kernel_launch(void* const* d_in, const int* in_sizes, int n_in,
                              void* d_out, int out_size) {
    const float* x     = (const float*)d_in[0];
    // d_in[1] = edge_attr (ignored by SAGEConv)
    const int*   ei    = (const int*)d_in[2];
    const int*   srcE  = ei;
    const int*   dstE  = ei + N_EDGES;
    const int*   batch = (const int*)d_in[3];
    const float* Wl    = (const float*)d_in[4];
    const float* bl    = (const float*)d_in[5];
    const float* Wr    = (const float*)d_in[6];
    const float* W1    = (const float*)d_in[7];
    const float* b1    = (const float*)d_in[8];
    const float* W2    = (const float*)d_in[9];
    const float* b2    = (const float*)d_in[10];
    float* out = (float*)d_out;

    int *p_cnt, *p_row, *p_loc, *p_csr, *p_bsum;
    float *p_mean, *p_h0, *p_h1, *p_btile, *p_wblob;
    cudaGetSymbolAddress((void**)&p_cnt, g_cnt);
    cudaGetSymbolAddress((void**)&p_row, g_row);
    cudaGetSymbolAddress((void**)&p_loc, g_loc);
    cudaGetSymbolAddress((void**)&p_csr, g_csr);
    cudaGetSymbolAddress((void**)&p_bsum, g_bsum);
    cudaGetSymbolAddress((void**)&p_mean, g_mean);
    cudaGetSymbolAddress((void**)&p_h0, g_h0);
    cudaGetSymbolAddress((void**)&p_h1, g_h1);
    cudaGetSymbolAddress((void**)&p_btile, g_btile);
    cudaGetSymbolAddress((void**)&p_wblob, g_Wblob);

    static int smem_set = 0;
    if (!smem_set) {
        cudaFuncSetAttribute(gemm_wmma_kernel,
                             cudaFuncAttributeMaxDynamicSharedMemorySize, GEMM_SMEM);
        smem_set = 1;
    }

    const int TB = 256;
    const int edge4_blocks = (N_EDGES / 4 + TB - 1) / TB;
    const int warp_node_blocks = (N_NODES * 32 + TB - 1) / TB;
    const int gemm_blocks = N_PAD / 64;   // 782

    // CSR build: ONE atomic pass, then scan, then atomic-free scatter
    cudaMemsetAsync(p_cnt, 0, N_NODES * sizeof(int), 0);
    count_loc_kernel<<<edge4_blocks, TB>>>(dstE, p_cnt, p_loc);
    scan_partial_kernel<<<SCAN_NB, SCAN_B>>>(p_cnt, p_bsum);
    scan_apply_kernel<<<SCAN_NB, SCAN_B>>>(p_cnt, p_bsum, p_row);
    fill_csr_kernel<<<edge4_blocks, TB>>>(srcE, dstE, p_loc, p_row, p_csr);

    // precompute tf32-rounded W blobs + bias tiles
    prep_w_kernel<<<(N_LAYERS * 2 * 128 * 32 + TB - 1) / TB, TB>>>(Wl, Wr, p_wblob);
    prep_bias_kernel<<<(N_LAYERS * 16 * HID + TB - 1) / TB, TB>>>(bl, p_btile);

    const float* cur = x;
    float* bufs[2] = {p_h0, p_h1};
    for (int l = 0; l < N_LAYERS; l++) {
        aggregate_kernel<<<warp_node_blocks, TB>>>(cur, p_mean);
        gemm_wmma_kernel<<<gemm_blocks, TB, GEMM_SMEM>>>(
            cur, p_mean, p_wblob + (size_t)(l * 2) * B_ELEMS,
            p_btile + l * 16 * HID, bufs[l & 1]);
        cur = bufs[l & 1];
    }

    pool_mlp_kernel<<<N_GRAPHS, HID>>>(cur, batch, W1, b1, W2, b2, out);
}